// round 7
// baseline (speedup 1.0000x reference)
#include <cuda_runtime.h>
#include <cuda_fp16.h>
#include <math.h>

#define BATCH   16384
#define HD      256
#define SAMPLES 16
#define MROWS   128
#define NLAYER  3
#define TOTCH   24          // 3 layers x 8 chunks of K=32
#define NTHREADS 1024

typedef unsigned int u32;

// ---------------- global scratch: W^T split into fp16 hi/lo planes
__device__ __align__(16) __half g_Whi[NLAYER * HD * HD];
__device__ __align__(16) __half g_Wlo[NLAYER * HD * HD];

__global__ void prep_split(const float* __restrict__ W1,
                           const float* __restrict__ W2,
                           const float* __restrict__ W3) {
    int b = blockIdx.x;               // 0..767
    int layer = b >> 8, n = b & 255, k = threadIdx.x;
    const float* W = layer == 0 ? W1 : (layer == 1 ? W2 : W3);
    float v = W[k * HD + n];
    __half hi = __float2half_rn(v);
    __half lo = __float2half_rn(v - __half2float(hi));
    g_Whi[(layer * HD + n) * HD + k] = hi;
    g_Wlo[(layer * HD + n) * HD + k] = lo;
}

// ---------------- smem layout (bytes)
#define SROW    528          // 256 halfs + 16B pad (33 chunks, coprime 8)
#define WROW    80           // 32 halfs + 16B pad  (5 chunks, coprime 8)
#define SM_SHI  0            // 128*528 = 67584
#define SM_SLO  67584        // 67584            -> 135168
#define SM_WB   135168       // 2 bufs x 2 planes x 256*80 = 81920 -> 217088
#define WB_BUF  40960
#define WB_LO   20480
#define SM_BIAS 217088       // 3*1024 -> 220160
#define SM_WO   220160       // 2048   -> 222208
#define SM_OUT  222208       // 1024   -> 223232
#define SM_TOT  223232

__device__ __forceinline__ u32 s2u(const void* p) { return (u32)__cvta_generic_to_shared(p); }

__device__ __forceinline__ void cpasync16(u32 dst, const void* src) {
    asm volatile("cp.async.cg.shared.global [%0], [%1], 16;" :: "r"(dst), "l"(src));
}
__device__ __forceinline__ void ldsm4(u32* d, u32 addr) {
    asm volatile("ldmatrix.sync.aligned.m8n8.x4.shared.b16 {%0,%1,%2,%3}, [%4];"
                 : "=r"(d[0]), "=r"(d[1]), "=r"(d[2]), "=r"(d[3]) : "r"(addr));
}
__device__ __forceinline__ void mma16816(float* c, const u32* a, u32 b0, u32 b1) {
    asm volatile("mma.sync.aligned.m16n8k16.row.col.f32.f16.f16.f32 "
                 "{%0,%1,%2,%3},{%4,%5,%6,%7},{%8,%9},{%0,%1,%2,%3};"
                 : "+f"(c[0]), "+f"(c[1]), "+f"(c[2]), "+f"(c[3])
                 : "r"(a[0]), "r"(a[1]), "r"(a[2]), "r"(a[3]), "r"(b0), "r"(b1));
}
__device__ __forceinline__ float ftanh(float u) {
    float a = fabsf(u);
    float t = __expf(-2.f * a);
    float h = __fdividef(1.f - t, 1.f + t);
    return copysignf(h, u);
}
// split store: hi + lo planes at (row, k) (k even, 2 values)
__device__ __forceinline__ void store_split(char* smem, int row, int k,
                                            float vx, float vy) {
    __half hx = __float2half_rn(vx), hy = __float2half_rn(vy);
    float lx = vx - __half2float(hx), ly = vy - __half2float(hy);
    __half2 hp = __halves2half2(hx, hy);
    __half2 lp = __halves2half2(__float2half_rn(lx), __float2half_rn(ly));
    *(u32*)(smem + SM_SHI + row * SROW + k * 2) = *(u32*)&hp;
    *(u32*)(smem + SM_SLO + row * SROW + k * 2) = *(u32*)&lp;
}

// one K=32 chunk of W^T (both planes): 1024 transfers/plane; 1024 threads.
__device__ __forceinline__ void load_chunk(char* smem, int cg, int tid) {
    const int layer = cg >> 3, c = cg & 7, bsel = cg & 1;
    const __half* sh = g_Whi + layer * (HD * HD) + c * 32;
    const __half* sl = g_Wlo + layer * (HD * HD) + c * 32;
    const u32 dH = s2u(smem + SM_WB) + (u32)(bsel * WB_BUF);
    const u32 dL = dH + WB_LO;
    const int n = tid >> 2, s = tid & 3;
    const u32 off = (u32)(n * WROW + s * 16);
    cpasync16(dH + off, sh + n * HD + s * 8);
    cpasync16(dL + off, sl + n * HD + s * 8);
    asm volatile("cp.async.commit_group;");
}

__global__ __launch_bounds__(NTHREADS, 1)
void grad_kernel(const float* __restrict__ x,
                 const float* __restrict__ W0, const float* __restrict__ b0,
                 const float* __restrict__ b1, const float* __restrict__ b2,
                 const float* __restrict__ b3,
                 const float* __restrict__ Wo, const float* __restrict__ bo,
                 float* __restrict__ out) {
    extern __shared__ __align__(16) char smem[];
    const int tid  = threadIdx.x;
    const int wid  = tid >> 5;
    const int lane = tid & 31;
    const int wm = wid & 3, wn = wid >> 2;       // 4 m-warps x 8 n-warps
    const int m0 = wm * 32, nb0 = wn * 32;       // warp tile 32x32
    const int s0 = blockIdx.x * SAMPLES;

    // ---- stage bias + Wo
    if (tid < HD) {
        ((float*)(smem + SM_BIAS))[tid]        = b1[tid];
        ((float*)(smem + SM_BIAS + 1024))[tid] = b2[tid];
        ((float*)(smem + SM_BIAS + 2048))[tid] = b3[tid];
    }
    if (tid < 512) ((float*)(smem + SM_WO))[tid] = Wo[tid];

    load_chunk(smem, 0, tid);   // prefetch overlaps layer0

    // ---- layer 0: 4 -> 256 jet, write split planes (64 threads per sample)
    {
        const int samp = tid >> 6, kg = tid & 63;
        const float4 xv = __ldg((const float4*)x + (s0 + samp));
#pragma unroll
        for (int jp = 0; jp < 2; jp++) {
            const int k = kg * 4 + jp * 2;
            float vv[2][8];
#pragma unroll
            for (int e = 0; e < 2; e++) {
                const int ke = k + e;
                float w0 = __ldg(W0 + 0 * HD + ke), w1 = __ldg(W0 + 1 * HD + ke);
                float w2 = __ldg(W0 + 2 * HD + ke), w3 = __ldg(W0 + 3 * HD + ke);
                float u0 = __ldg(b0 + ke) + xv.x * w0 + xv.y * w1 + xv.z * w2 + xv.w * w3;
                float h = ftanh(u0), d = 1.f - h * h;
                vv[e][0] = h;
                vv[e][1] = d * w0; vv[e][2] = d * w1; vv[e][3] = d * w2; vv[e][4] = d * w3;
                float c2 = -2.f * h * d;
                vv[e][5] = c2 * w0 * w0; vv[e][6] = c2 * w1 * w1; vv[e][7] = c2 * w2 * w2;
            }
#pragma unroll
            for (int ch = 0; ch < 8; ch++)
                store_split(smem, samp * 8 + ch, k, vv[0][ch], vv[1][ch]);
        }
    }
    __syncthreads();

    // ---- lane bases for ldmatrix
    const int lt = lane >> 3, lr = lane & 7;
    const u32 aBase = (u32)((m0 + ((lt & 1) << 3) + lr) * SROW + ((lt >> 1) << 4));
    const u32 aHi = s2u(smem + SM_SHI) + aBase;
    const u32 aLo = s2u(smem + SM_SLO) + aBase;
    const u32 bOff = (u32)((nb0 + ((lt >> 1) << 3) + lr) * WROW + ((lt & 1) << 4));
    const int q = lane & 3, ch = lane >> 2;
    const int srcl = (ch >= 5) ? (((ch - 4) << 2) + q) : lane;

    float acc[2][4][4];     // [m-tile][n8][frag]

    for (int L = 0; L < NLAYER; L++) {
#pragma unroll
        for (int mt = 0; mt < 2; mt++)
#pragma unroll
            for (int nt = 0; nt < 4; nt++)
#pragma unroll
                for (int j = 0; j < 4; j++) acc[mt][nt][j] = 0.f;

        for (int c = 0; c < 8; c++) {
            const int cg = L * 8 + c;
            if (c > 0) __syncthreads();          // prior chunk's reads done
            if (cg + 1 < TOTCH) {
                load_chunk(smem, cg + 1, tid);
                asm volatile("cp.async.wait_group 1;");
            } else {
                asm volatile("cp.async.wait_group 0;");
            }
            __syncthreads();                     // buffer cg filled & visible

            const u32 wb = s2u(smem + SM_WB) + (u32)((cg & 1) * WB_BUF) + bOff;
#pragma unroll
            for (int kt = 0; kt < 2; kt++) {
                const u32 ka = (u32)(c * 64 + kt * 32);
                const u32 wk = wb + (u32)(kt * 32);
                u32 B0h[4], B0l[4], B1h[4], B1l[4];
                ldsm4(B0h, wk);
                ldsm4(B0l, wk + WB_LO);
                ldsm4(B1h, wk + 16 * WROW);
                ldsm4(B1l, wk + 16 * WROW + WB_LO);
                u32 Af[2][4];
                ldsm4(Af[0], aHi + ka);
                ldsm4(Af[1], aHi + 16 * SROW + ka);
#pragma unroll
                for (int mt = 0; mt < 2; mt++) {
                    mma16816(acc[mt][0], Af[mt], B0h[0], B0h[1]);
                    mma16816(acc[mt][0], Af[mt], B0l[0], B0l[1]);
                    mma16816(acc[mt][1], Af[mt], B0h[2], B0h[3]);
                    mma16816(acc[mt][1], Af[mt], B0l[2], B0l[3]);
                    mma16816(acc[mt][2], Af[mt], B1h[0], B1h[1]);
                    mma16816(acc[mt][2], Af[mt], B1l[0], B1l[1]);
                    mma16816(acc[mt][3], Af[mt], B1h[2], B1h[3]);
                    mma16816(acc[mt][3], Af[mt], B1l[2], B1l[3]);
                }
                ldsm4(Af[0], aLo + ka);                 // overwrite hi frags
                ldsm4(Af[1], aLo + 16 * SROW + ka);
#pragma unroll
                for (int mt = 0; mt < 2; mt++) {
                    mma16816(acc[mt][0], Af[mt], B0h[0], B0h[1]);
                    mma16816(acc[mt][1], Af[mt], B0h[2], B0h[3]);
                    mma16816(acc[mt][2], Af[mt], B1h[0], B1h[1]);
                    mma16816(acc[mt][3], Af[mt], B1h[2], B1h[3]);
                }
            }
        }
        __syncthreads();   // all A-frag reads of S done before epilogue writes

        // ---- epilogue: tanh-jet in registers, write split planes
        const float* bs = (const float*)(smem + SM_BIAS) + L * HD;
#pragma unroll
        for (int mt = 0; mt < 2; mt++) {
#pragma unroll
            for (int nt = 0; nt < 4; nt++) {
                const int n = nb0 + nt * 8 + 2 * q;
                const float2 bn = *(const float2*)(bs + n);
#pragma unroll
                for (int pr = 0; pr < 2; pr++) {     // pr: sample pair (rows +0 / +8)
                    float ux = acc[mt][nt][pr * 2 + 0], uy = acc[mt][nt][pr * 2 + 1];
                    float u0x = __shfl_sync(0xffffffffu, ux, q);
                    float u0y = __shfl_sync(0xffffffffu, uy, q);
                    float u1x = __shfl_sync(0xffffffffu, ux, srcl);
                    float u1y = __shfl_sync(0xffffffffu, uy, srcl);
                    float hx = ftanh(u0x + bn.x), hy = ftanh(u0y + bn.y);
                    float dx = 1.f - hx * hx, dy = 1.f - hy * hy;
                    float vx, vy;
                    if (ch == 0)      { vx = hx; vy = hy; }
                    else if (ch < 5)  { vx = dx * ux; vy = dy * uy; }
                    else {
                        vx = dx * (ux - 2.f * hx * u1x * u1x);
                        vy = dy * (uy - 2.f * hy * u1y * u1y);
                    }
                    store_split(smem, m0 + mt * 16 + pr * 8 + ch, n, vx, vy);
                }
            }
        }
        __syncthreads();
    }

    // ---- output head: 128 rows x 2 outs; 8 threads per row (32 k each)
    {
        const int m = tid >> 3, kq = tid & 7;
        const char* ph = smem + SM_SHI + m * SROW;
        const char* pl = smem + SM_SLO + m * SROW;
        const float* wos = (const float*)(smem + SM_WO);
        float o0 = 0.f, o1 = 0.f;
#pragma unroll 4
        for (int kk = 0; kk < 16; kk++) {
            const int k = kq * 32 + ((kk + kq * 2) & 15) * 2;   // rotate: no bank clash
            u32 hp = *(const u32*)(ph + k * 2);
            u32 lp = *(const u32*)(pl + k * 2);
            float2 vh = __half22float2(*(__half2*)&hp);
            float2 vl = __half22float2(*(__half2*)&lp);
            float v0 = vh.x + vl.x, v1 = vh.y + vl.y;
            float2 w0 = *(const float2*)(wos + k * 2);
            float2 w1 = *(const float2*)(wos + k * 2 + 2);
            o0 += v0 * w0.x + v1 * w1.x;
            o1 += v0 * w0.y + v1 * w1.y;
        }
        o0 += __shfl_xor_sync(0xffffffffu, o0, 1);
        o0 += __shfl_xor_sync(0xffffffffu, o0, 2);
        o0 += __shfl_xor_sync(0xffffffffu, o0, 4);
        o1 += __shfl_xor_sync(0xffffffffu, o1, 1);
        o1 += __shfl_xor_sync(0xffffffffu, o1, 2);
        o1 += __shfl_xor_sync(0xffffffffu, o1, 4);
        if (kq == 0) {
            if ((m & 7) == 0) { o0 += __ldg(bo); o1 += __ldg(bo + 1); }
            ((float*)(smem + SM_OUT))[m * 2 + 0] = o0;
            ((float*)(smem + SM_OUT))[m * 2 + 1] = o1;
        }
    }
    __syncthreads();

    // ---- per-sample combine + stores
    if (tid < SAMPLES) {
        const float* ob = (const float*)(smem + SM_OUT) + tid * 16;  // [ch][dout]
        float c  = ob[0], Fi = ob[1];
        float cj[4], Fj[4];
#pragma unroll
        for (int i = 0; i < 4; i++) { cj[i] = ob[(1 + i) * 2]; Fj[i] = ob[(1 + i) * 2 + 1]; }
        float trHc = 0.f, FiLap = 0.f;
#pragma unroll
        for (int i = 0; i < 3; i++) { trHc += ob[(5 + i) * 2]; FiLap += ob[(5 + i) * 2 + 1]; }
        float dotg = cj[0] * Fj[0] + cj[1] * Fj[1] + cj[2] * Fj[2];
        float sumg = cj[0] + cj[1] + cj[2];
        float jdiv = -trHc - (dotg + c * FiLap) + 0.1f * sumg;

        const int idx = s0 + tid;
        out[idx]                     = c;
        out[BATCH + idx]             = cj[3];
        out[2 * BATCH + idx * 3 + 0] = cj[0];
        out[2 * BATCH + idx * 3 + 1] = cj[1];
        out[2 * BATCH + idx * 3 + 2] = cj[2];
        out[5 * BATCH + idx]         = Fi;
        out[6 * BATCH + idx * 3 + 0] = Fj[0];
        out[6 * BATCH + idx * 3 + 1] = Fj[1];
        out[6 * BATCH + idx * 3 + 2] = Fj[2];
        out[9 * BATCH + idx]         = FiLap;
        out[10 * BATCH + idx]        = jdiv;
    }
}

extern "C" void kernel_launch(void* const* d_in, const int* in_sizes, int n_in,
                              void* d_out, int out_size) {
    const float* x  = (const float*)d_in[0];
    const float* W0 = (const float*)d_in[1];
    const float* b0 = (const float*)d_in[2];
    const float* W1 = (const float*)d_in[3];
    const float* b1 = (const float*)d_in[4];
    const float* W2 = (const float*)d_in[5];
    const float* b2 = (const float*)d_in[6];
    const float* W3 = (const float*)d_in[7];
    const float* b3 = (const float*)d_in[8];
    const float* Wo = (const float*)d_in[9];
    const float* bo = (const float*)d_in[10];

    prep_split<<<NLAYER * HD, HD>>>(W1, W2, W3);

    cudaFuncSetAttribute(grad_kernel, cudaFuncAttributeMaxDynamicSharedMemorySize, SM_TOT);
    grad_kernel<<<BATCH / SAMPLES, NTHREADS, SM_TOT>>>(x, W0, b0, b1, b2, b3,
                                                       Wo, bo, (float*)d_out);
}

// round 9
// speedup vs baseline: 2.1050x; 2.1050x over previous
#include <cuda_runtime.h>
#include <cuda_fp16.h>
#include <math.h>

#define BATCH   16384
#define HD      256
#define SAMPLES 16
#define MROWS   128
#define NLAYER  3
#define TOTCH   24          // 3 layers x 8 chunks of K=32
#define NTHREADS 1024

typedef unsigned int u32;

// ---------------- global scratch: W^T rounded to fp16 (hi plane only)
__device__ __align__(16) __half g_Whi[NLAYER * HD * HD];

__global__ void prep_split(const float* __restrict__ W1,
                           const float* __restrict__ W2,
                           const float* __restrict__ W3) {
    int b = blockIdx.x;               // 0..767
    int layer = b >> 8, n = b & 255, k = threadIdx.x;
    const float* W = layer == 0 ? W1 : (layer == 1 ? W2 : W3);
    g_Whi[(layer * HD + n) * HD + k] = __float2half_rn(W[k * HD + n]);
}

// ---------------- smem layout (bytes)
#define SROW    528          // 256 halfs + 16B pad (33 chunks, coprime 8)
#define WROW    80           // 32 halfs + 16B pad  (5 chunks, coprime 8)
#define SM_SHI  0            // 128*528 = 67584
#define SM_SLO  67584        //                  -> 135168
#define SM_WB   135168       // 2 bufs x 256*80 = 40960 -> 176128
#define WB_BUF  20480
#define SM_BIAS 176128       // 3*1024 -> 179200
#define SM_WO   179200       // 2048   -> 181248
#define SM_OUT  181248       // 1024   -> 182272
#define SM_TOT  182272

__device__ __forceinline__ u32 s2u(const void* p) { return (u32)__cvta_generic_to_shared(p); }

__device__ __forceinline__ void cpasync16(u32 dst, const void* src) {
    asm volatile("cp.async.cg.shared.global [%0], [%1], 16;" :: "r"(dst), "l"(src));
}
__device__ __forceinline__ void ldsm4(u32* d, u32 addr) {
    asm volatile("ldmatrix.sync.aligned.m8n8.x4.shared.b16 {%0,%1,%2,%3}, [%4];"
                 : "=r"(d[0]), "=r"(d[1]), "=r"(d[2]), "=r"(d[3]) : "r"(addr));
}
__device__ __forceinline__ void mma16816(float* c, const u32* a, u32 b0, u32 b1) {
    asm volatile("mma.sync.aligned.m16n8k16.row.col.f32.f16.f16.f32 "
                 "{%0,%1,%2,%3},{%4,%5,%6,%7},{%8,%9},{%0,%1,%2,%3};"
                 : "+f"(c[0]), "+f"(c[1]), "+f"(c[2]), "+f"(c[3])
                 : "r"(a[0]), "r"(a[1]), "r"(a[2]), "r"(a[3]), "r"(b0), "r"(b1));
}
__device__ __forceinline__ float ftanh(float u) {
    float a = fabsf(u);
    float t = __expf(-2.f * a);
    float h = __fdividef(1.f - t, 1.f + t);
    return copysignf(h, u);
}
// split store: hi + lo planes at (row, k) (k even, 2 values)
__device__ __forceinline__ void store_split(char* smem, int row, int k,
                                            float vx, float vy) {
    __half hx = __float2half_rn(vx), hy = __float2half_rn(vy);
    float lx = vx - __half2float(hx), ly = vy - __half2float(hy);
    __half2 hp = __halves2half2(hx, hy);
    __half2 lp = __halves2half2(__float2half_rn(lx), __float2half_rn(ly));
    *(u32*)(smem + SM_SHI + row * SROW + k * 2) = *(u32*)&hp;
    *(u32*)(smem + SM_SLO + row * SROW + k * 2) = *(u32*)&lp;
}

// one K=32 chunk of W^T (hi plane): 256 rows x 4 x 16B = 1024 transfers;
// 1024 threads, one each.
__device__ __forceinline__ void load_chunk(char* smem, int cg, int tid) {
    const int layer = cg >> 3, c = cg & 7, bsel = cg & 1;
    const __half* sh = g_Whi + layer * (HD * HD) + c * 32;
    const u32 dH = s2u(smem + SM_WB) + (u32)(bsel * WB_BUF);
    const int n = tid >> 2, s = tid & 3;
    cpasync16(dH + (u32)(n * WROW + s * 16), sh + n * HD + s * 8);
    asm volatile("cp.async.commit_group;");
}

__global__ __launch_bounds__(NTHREADS, 1)
void grad_kernel(const float* __restrict__ x,
                 const float* __restrict__ W0, const float* __restrict__ b0,
                 const float* __restrict__ b1, const float* __restrict__ b2,
                 const float* __restrict__ b3,
                 const float* __restrict__ Wo, const float* __restrict__ bo,
                 float* __restrict__ out) {
    extern __shared__ __align__(16) char smem[];
    const int tid  = threadIdx.x;
    const int wid  = tid >> 5;
    const int lane = tid & 31;
    const int wm = wid & 7, wn = wid >> 3;       // 8 m-tiles x 4 n-blocks
    const int m0 = wm * 16, nb0 = wn * 64;       // warp tile 16x64
    const int s0 = blockIdx.x * SAMPLES;

    // ---- stage bias + Wo
    if (tid < HD) {
        ((float*)(smem + SM_BIAS))[tid]        = b1[tid];
        ((float*)(smem + SM_BIAS + 1024))[tid] = b2[tid];
        ((float*)(smem + SM_BIAS + 2048))[tid] = b3[tid];
    }
    if (tid < 512) ((float*)(smem + SM_WO))[tid] = Wo[tid];

    load_chunk(smem, 0, tid);   // prefetch overlaps layer0

    // ---- layer 0: 4 -> 256 jet, write split planes (64 threads per sample)
    {
        const int samp = tid >> 6, kg = tid & 63;
        const float4 xv = __ldg((const float4*)x + (s0 + samp));
#pragma unroll
        for (int jp = 0; jp < 2; jp++) {
            const int k = kg * 4 + jp * 2;
            float vv[2][8];
#pragma unroll
            for (int e = 0; e < 2; e++) {
                const int ke = k + e;
                float w0 = __ldg(W0 + 0 * HD + ke), w1 = __ldg(W0 + 1 * HD + ke);
                float w2 = __ldg(W0 + 2 * HD + ke), w3 = __ldg(W0 + 3 * HD + ke);
                float u0 = __ldg(b0 + ke) + xv.x * w0 + xv.y * w1 + xv.z * w2 + xv.w * w3;
                float h = ftanh(u0), d = 1.f - h * h;
                vv[e][0] = h;
                vv[e][1] = d * w0; vv[e][2] = d * w1; vv[e][3] = d * w2; vv[e][4] = d * w3;
                float c2 = -2.f * h * d;
                vv[e][5] = c2 * w0 * w0; vv[e][6] = c2 * w1 * w1; vv[e][7] = c2 * w2 * w2;
            }
#pragma unroll
            for (int ch = 0; ch < 8; ch++)
                store_split(smem, samp * 8 + ch, k, vv[0][ch], vv[1][ch]);
        }
    }
    __syncthreads();

    // ---- lane bases for ldmatrix
    const int lt = lane >> 3, lr = lane & 7;
    const u32 aBase = (u32)((m0 + ((lt & 1) << 3) + lr) * SROW + ((lt >> 1) << 4));
    const u32 aHi = s2u(smem + SM_SHI) + aBase;
    const u32 aLo = s2u(smem + SM_SLO) + aBase;
    const u32 bOff = (u32)((nb0 + ((lt >> 1) << 3) + lr) * WROW + ((lt & 1) << 4));
    const int q = lane & 3, ch = lane >> 2;
    const int srcl = (ch >= 5) ? (((ch - 4) << 2) + q) : lane;

    float acc[8][4];

    for (int L = 0; L < NLAYER; L++) {
#pragma unroll
        for (int nt = 0; nt < 8; nt++)
#pragma unroll
            for (int j = 0; j < 4; j++) acc[nt][j] = 0.f;

        for (int c = 0; c < 8; c++) {
            const int cg = L * 8 + c;
            if (c > 0) __syncthreads();          // prior chunk's reads done
            if (cg + 1 < TOTCH) {
                load_chunk(smem, cg + 1, tid);
                asm volatile("cp.async.wait_group 1;");
            } else {
                asm volatile("cp.async.wait_group 0;");
            }
            __syncthreads();                     // buffer cg filled & visible

            const u32 wb = s2u(smem + SM_WB) + (u32)((cg & 1) * WB_BUF) + bOff;
#pragma unroll
            for (int kt = 0; kt < 2; kt++) {
                const u32 ka = (u32)(c * 64 + kt * 32);
                u32 Ah[4], Al[4];
                ldsm4(Ah, aHi + ka);
                ldsm4(Al, aLo + ka);
                const u32 wk = wb + (u32)(kt * 32);
#pragma unroll
                for (int np = 0; np < 4; np++) {
                    u32 Bh[4];
                    ldsm4(Bh, wk + (u32)(np * 16 * WROW));
                    mma16816(acc[2 * np],     Ah, Bh[0], Bh[1]);
                    mma16816(acc[2 * np],     Al, Bh[0], Bh[1]);
                    mma16816(acc[2 * np + 1], Ah, Bh[2], Bh[3]);
                    mma16816(acc[2 * np + 1], Al, Bh[2], Bh[3]);
                }
            }
        }
        __syncthreads();   // all A-frag reads of S done before epilogue writes

        // ---- epilogue: tanh-jet in registers, write split planes
        const float* bs = (const float*)(smem + SM_BIAS) + L * HD;
#pragma unroll
        for (int nt = 0; nt < 8; nt++) {
            const int n = nb0 + nt * 8 + 2 * q;
            const float2 bn = *(const float2*)(bs + n);
#pragma unroll
            for (int sh = 0; sh < 2; sh++) {
                float ux = acc[nt][sh * 2 + 0], uy = acc[nt][sh * 2 + 1];
                float u0x = __shfl_sync(0xffffffffu, ux, q);
                float u0y = __shfl_sync(0xffffffffu, uy, q);
                float u1x = __shfl_sync(0xffffffffu, ux, srcl);
                float u1y = __shfl_sync(0xffffffffu, uy, srcl);
                float hx = ftanh(u0x + bn.x), hy = ftanh(u0y + bn.y);
                float dx = 1.f - hx * hx, dy = 1.f - hy * hy;
                float vx, vy;
                if (ch == 0)      { vx = hx; vy = hy; }
                else if (ch < 5)  { vx = dx * ux; vy = dy * uy; }
                else {
                    vx = dx * (ux - 2.f * hx * u1x * u1x);
                    vy = dy * (uy - 2.f * hy * u1y * u1y);
                }
                store_split(smem, m0 + sh * 8 + ch, n, vx, vy);
            }
        }
        __syncthreads();
    }

    // ---- output head: 128 rows x 2 outs; 8 threads per row (32 k each)
    {
        const int m = tid >> 3, kq = tid & 7;
        const char* ph = smem + SM_SHI + m * SROW;
        const char* pl = smem + SM_SLO + m * SROW;
        const float* wos = (const float*)(smem + SM_WO);
        float o0 = 0.f, o1 = 0.f;
#pragma unroll 4
        for (int kk = 0; kk < 16; kk++) {
            const int k = kq * 32 + ((kk + kq * 2) & 15) * 2;   // rotate: no bank clash
            u32 hp = *(const u32*)(ph + k * 2);
            u32 lp = *(const u32*)(pl + k * 2);
            float2 vh = __half22float2(*(__half2*)&hp);
            float2 vl = __half22float2(*(__half2*)&lp);
            float v0 = vh.x + vl.x, v1 = vh.y + vl.y;
            float2 w0 = *(const float2*)(wos + k * 2);
            float2 w1 = *(const float2*)(wos + k * 2 + 2);
            o0 += v0 * w0.x + v1 * w1.x;
            o1 += v0 * w0.y + v1 * w1.y;
        }
        o0 += __shfl_xor_sync(0xffffffffu, o0, 1);
        o0 += __shfl_xor_sync(0xffffffffu, o0, 2);
        o0 += __shfl_xor_sync(0xffffffffu, o0, 4);
        o1 += __shfl_xor_sync(0xffffffffu, o1, 1);
        o1 += __shfl_xor_sync(0xffffffffu, o1, 2);
        o1 += __shfl_xor_sync(0xffffffffu, o1, 4);
        if (kq == 0) {
            if ((m & 7) == 0) { o0 += __ldg(bo); o1 += __ldg(bo + 1); }
            ((float*)(smem + SM_OUT))[m * 2 + 0] = o0;
            ((float*)(smem + SM_OUT))[m * 2 + 1] = o1;
        }
    }
    __syncthreads();

    // ---- per-sample combine + stores
    if (tid < SAMPLES) {
        const float* ob = (const float*)(smem + SM_OUT) + tid * 16;  // [ch][dout]
        float c  = ob[0], Fi = ob[1];
        float cj[4], Fj[4];
#pragma unroll
        for (int i = 0; i < 4; i++) { cj[i] = ob[(1 + i) * 2]; Fj[i] = ob[(1 + i) * 2 + 1]; }
        float trHc = 0.f, FiLap = 0.f;
#pragma unroll
        for (int i = 0; i < 3; i++) { trHc += ob[(5 + i) * 2]; FiLap += ob[(5 + i) * 2 + 1]; }
        float dotg = cj[0] * Fj[0] + cj[1] * Fj[1] + cj[2] * Fj[2];
        float sumg = cj[0] + cj[1] + cj[2];
        float jdiv = -trHc - (dotg + c * FiLap) + 0.1f * sumg;

        const int idx = s0 + tid;
        out[idx]                     = c;
        out[BATCH + idx]             = cj[3];
        out[2 * BATCH + idx * 3 + 0] = cj[0];
        out[2 * BATCH + idx * 3 + 1] = cj[1];
        out[2 * BATCH + idx * 3 + 2] = cj[2];
        out[5 * BATCH + idx]         = Fi;
        out[6 * BATCH + idx * 3 + 0] = Fj[0];
        out[6 * BATCH + idx * 3 + 1] = Fj[1];
        out[6 * BATCH + idx * 3 + 2] = Fj[2];
        out[9 * BATCH + idx]         = FiLap;
        out[10 * BATCH + idx]        = jdiv;
    }
}

extern "C" void kernel_launch(void* const* d_in, const int* in_sizes, int n_in,
                              void* d_out, int out_size) {
    const float* x  = (const float*)d_in[0];
    const float* W0 = (const float*)d_in[1];
    const float* b0 = (const float*)d_in[2];
    const float* W1 = (const float*)d_in[3];
    const float* b1 = (const float*)d_in[4];
    const float* W2 = (const float*)d_in[5];
    const float* b2 = (const float*)d_in[6];
    const float* W3 = (const float*)d_in[7];
    const float* b3 = (const float*)d_in[8];
    const float* Wo = (const float*)d_in[9];
    const float* bo = (const float*)d_in[10];

    prep_split<<<NLAYER * HD, HD>>>(W1, W2, W3);

    cudaFuncSetAttribute(grad_kernel, cudaFuncAttributeMaxDynamicSharedMemorySize, SM_TOT);
    grad_kernel<<<BATCH / SAMPLES, NTHREADS, SM_TOT>>>(x, W0, b0, b1, b2, b3,
                                                       Wo, bo, (float*)d_out);
}

// round 10
// speedup vs baseline: 2.1527x; 1.0226x over previous
#include <cuda_runtime.h>
#include <cuda_fp16.h>
#include <math.h>

#define BATCH   16384
#define HD      256
#define SAMPLES 16
#define MROWS   128
#define NLAYER  3
#define TOTCH   24          // 3 layers x 8 chunks of K=32
#define NTHREADS 1024

typedef unsigned int u32;

// ---------------- global scratch: W^T rounded to fp16
__device__ __align__(16) __half g_Whi[NLAYER * HD * HD];

__global__ void prep_split(const float* __restrict__ W1,
                           const float* __restrict__ W2,
                           const float* __restrict__ W3) {
    int b = blockIdx.x;               // 0..767
    int layer = b >> 8, n = b & 255, k = threadIdx.x;
    const float* W = layer == 0 ? W1 : (layer == 1 ? W2 : W3);
    g_Whi[(layer * HD + n) * HD + k] = __float2half_rn(W[k * HD + n]);
}

// ---------------- smem layout (bytes)
#define SROW    528          // 256 halfs + 16B pad (33 chunks, coprime 8)
#define WROW    80           // 32 halfs + 16B pad  (5 chunks, coprime 8)
#define SM_SHI  0            // 128*528 = 67584
#define SM_SLO  67584        //                  -> 135168
#define SM_WB   135168       // 4 bufs x 256*80 = 81920 -> 217088
#define WB_BUF  20480
#define SM_BIAS 217088       // 3*1024 -> 220160
#define SM_WO   220160       // 2048   -> 222208
#define SM_OUT  222208       // 1024   -> 223232
#define SM_TOT  223232

__device__ __forceinline__ u32 s2u(const void* p) { return (u32)__cvta_generic_to_shared(p); }

__device__ __forceinline__ void cpasync16(u32 dst, const void* src) {
    asm volatile("cp.async.cg.shared.global [%0], [%1], 16;" :: "r"(dst), "l"(src));
}
__device__ __forceinline__ void ldsm4(u32* d, u32 addr) {
    asm volatile("ldmatrix.sync.aligned.m8n8.x4.shared.b16 {%0,%1,%2,%3}, [%4];"
                 : "=r"(d[0]), "=r"(d[1]), "=r"(d[2]), "=r"(d[3]) : "r"(addr));
}
__device__ __forceinline__ void mma16816(float* c, const u32* a, u32 b0, u32 b1) {
    asm volatile("mma.sync.aligned.m16n8k16.row.col.f32.f16.f16.f32 "
                 "{%0,%1,%2,%3},{%4,%5,%6,%7},{%8,%9},{%0,%1,%2,%3};"
                 : "+f"(c[0]), "+f"(c[1]), "+f"(c[2]), "+f"(c[3])
                 : "r"(a[0]), "r"(a[1]), "r"(a[2]), "r"(a[3]), "r"(b0), "r"(b1));
}
__device__ __forceinline__ float ftanh(float u) {
    float a = fabsf(u);
    float t = __expf(-2.f * a);
    float h = __fdividef(1.f - t, 1.f + t);
    return copysignf(h, u);
}
// split store: hi + lo planes at (row, k) (k even, 2 values)
__device__ __forceinline__ void store_split(char* smem, int row, int k,
                                            float vx, float vy) {
    __half hx = __float2half_rn(vx), hy = __float2half_rn(vy);
    float lx = vx - __half2float(hx), ly = vy - __half2float(hy);
    __half2 hp = __halves2half2(hx, hy);
    __half2 lp = __halves2half2(__float2half_rn(lx), __float2half_rn(ly));
    *(u32*)(smem + SM_SHI + row * SROW + k * 2) = *(u32*)&hp;
    *(u32*)(smem + SM_SLO + row * SROW + k * 2) = *(u32*)&lp;
}

// one K=32 chunk of W^T: 256 rows x 4 x 16B = 1024 transfers; 1024 threads.
__device__ __forceinline__ void load_chunk(char* smem, int cg, int tid) {
    const int layer = cg >> 3, c = cg & 7, bsel = cg & 3;
    const __half* sh = g_Whi + layer * (HD * HD) + c * 32;
    const u32 dH = s2u(smem + SM_WB) + (u32)(bsel * WB_BUF);
    const int n = tid >> 2, s = tid & 3;
    cpasync16(dH + (u32)(n * WROW + s * 16), sh + n * HD + s * 8);
    asm volatile("cp.async.commit_group;");
}

__global__ __launch_bounds__(NTHREADS, 1)
void grad_kernel(const float* __restrict__ x,
                 const float* __restrict__ W0, const float* __restrict__ b0,
                 const float* __restrict__ b1, const float* __restrict__ b2,
                 const float* __restrict__ b3,
                 const float* __restrict__ Wo, const float* __restrict__ bo,
                 float* __restrict__ out) {
    extern __shared__ __align__(16) char smem[];
    const int tid  = threadIdx.x;
    const int wid  = tid >> 5;
    const int lane = tid & 31;
    const int wm = wid & 7, wn = wid >> 3;       // 8 m-tiles x 4 n-blocks
    const int m0 = wm * 16, nb0 = wn * 64;       // warp tile 16x64
    const int s0 = blockIdx.x * SAMPLES;

    // ---- stage bias + Wo
    if (tid < HD) {
        ((float*)(smem + SM_BIAS))[tid]        = b1[tid];
        ((float*)(smem + SM_BIAS + 1024))[tid] = b2[tid];
        ((float*)(smem + SM_BIAS + 2048))[tid] = b3[tid];
    }
    if (tid < 512) ((float*)(smem + SM_WO))[tid] = Wo[tid];

    // ---- prologue: prefetch chunks 0..2 (overlaps layer 0)
    load_chunk(smem, 0, tid);
    load_chunk(smem, 1, tid);
    load_chunk(smem, 2, tid);

    // ---- layer 0: 4 -> 256 jet, write split planes (64 threads per sample)
    {
        const int samp = tid >> 6, kg = tid & 63;
        const float4 xv = __ldg((const float4*)x + (s0 + samp));
#pragma unroll
        for (int jp = 0; jp < 2; jp++) {
            const int k = kg * 4 + jp * 2;
            float vv[2][8];
#pragma unroll
            for (int e = 0; e < 2; e++) {
                const int ke = k + e;
                float w0 = __ldg(W0 + 0 * HD + ke), w1 = __ldg(W0 + 1 * HD + ke);
                float w2 = __ldg(W0 + 2 * HD + ke), w3 = __ldg(W0 + 3 * HD + ke);
                float u0 = __ldg(b0 + ke) + xv.x * w0 + xv.y * w1 + xv.z * w2 + xv.w * w3;
                float h = ftanh(u0), d = 1.f - h * h;
                vv[e][0] = h;
                vv[e][1] = d * w0; vv[e][2] = d * w1; vv[e][3] = d * w2; vv[e][4] = d * w3;
                float c2 = -2.f * h * d;
                vv[e][5] = c2 * w0 * w0; vv[e][6] = c2 * w1 * w1; vv[e][7] = c2 * w2 * w2;
            }
#pragma unroll
            for (int ch = 0; ch < 8; ch++)
                store_split(smem, samp * 8 + ch, k, vv[0][ch], vv[1][ch]);
        }
    }
    __syncthreads();

    // ---- lane bases for ldmatrix
    const int lt = lane >> 3, lr = lane & 7;
    const u32 aBase = (u32)((m0 + ((lt & 1) << 3) + lr) * SROW + ((lt >> 1) << 4));
    const u32 aHi = s2u(smem + SM_SHI) + aBase;
    const u32 aLo = s2u(smem + SM_SLO) + aBase;
    const u32 bOff = (u32)((nb0 + ((lt >> 1) << 3) + lr) * WROW + ((lt & 1) << 4));
    const int q = lane & 3, ch = lane >> 2;
    const int srcl = (ch >= 5) ? (((ch - 4) << 2) + q) : lane;

    float acc[8][4];

    for (int L = 0; L < NLAYER; L++) {
#pragma unroll
        for (int nt = 0; nt < 8; nt++)
#pragma unroll
            for (int j = 0; j < 4; j++) acc[nt][j] = 0.f;

        for (int c = 0; c < 8; c++) {
            const int cg = L * 8 + c;
            // chunk cg landed once <=2 younger groups remain in flight
            asm volatile("cp.async.wait_group 2;");
            __syncthreads();   // all warps done with chunk cg-1; cg visible
            if (cg + 3 < TOTCH) load_chunk(smem, cg + 3, tid);  // buf (cg-1)&3

            const u32 wb = s2u(smem + SM_WB) + (u32)((cg & 3) * WB_BUF) + bOff;
#pragma unroll
            for (int kt = 0; kt < 2; kt++) {
                const u32 ka = (u32)(c * 64 + kt * 32);
                const u32 wk = wb + (u32)(kt * 32);
                u32 Ah[4], Al[4], B[4][4];
                ldsm4(Ah, aHi + ka);
                ldsm4(Al, aLo + ka);
#pragma unroll
                for (int np = 0; np < 4; np++)
                    ldsm4(B[np], wk + (u32)(np * 16 * WROW));
                // 8 independent MMAs on distinct accumulators (Ah pass)
#pragma unroll
                for (int np = 0; np < 4; np++) {
                    mma16816(acc[2 * np],     Ah, B[np][0], B[np][1]);
                    mma16816(acc[2 * np + 1], Ah, B[np][2], B[np][3]);
                }
                // 8 more (Al pass); per-acc order Ah->Al preserved (bitwise)
#pragma unroll
                for (int np = 0; np < 4; np++) {
                    mma16816(acc[2 * np],     Al, B[np][0], B[np][1]);
                    mma16816(acc[2 * np + 1], Al, B[np][2], B[np][3]);
                }
            }
        }
        __syncthreads();   // all A-frag reads of S done before epilogue writes

        // ---- epilogue: tanh-jet in registers, write split planes
        const float* bs = (const float*)(smem + SM_BIAS) + L * HD;
#pragma unroll
        for (int nt = 0; nt < 8; nt++) {
            const int n = nb0 + nt * 8 + 2 * q;
            const float2 bn = *(const float2*)(bs + n);
#pragma unroll
            for (int sh = 0; sh < 2; sh++) {
                float ux = acc[nt][sh * 2 + 0], uy = acc[nt][sh * 2 + 1];
                float u0x = __shfl_sync(0xffffffffu, ux, q);
                float u0y = __shfl_sync(0xffffffffu, uy, q);
                float u1x = __shfl_sync(0xffffffffu, ux, srcl);
                float u1y = __shfl_sync(0xffffffffu, uy, srcl);
                float hx = ftanh(u0x + bn.x), hy = ftanh(u0y + bn.y);
                float dx = 1.f - hx * hx, dy = 1.f - hy * hy;
                float vx, vy;
                if (ch == 0)      { vx = hx; vy = hy; }
                else if (ch < 5)  { vx = dx * ux; vy = dy * uy; }
                else {
                    vx = dx * (ux - 2.f * hx * u1x * u1x);
                    vy = dy * (uy - 2.f * hy * u1y * u1y);
                }
                store_split(smem, m0 + sh * 8 + ch, n, vx, vy);
            }
        }
        __syncthreads();
    }

    // ---- output head: 128 rows x 2 outs; 8 threads per row (32 k each)
    {
        const int m = tid >> 3, kq = tid & 7;
        const char* ph = smem + SM_SHI + m * SROW;
        const char* pl = smem + SM_SLO + m * SROW;
        const float* wos = (const float*)(smem + SM_WO);
        float o0 = 0.f, o1 = 0.f;
#pragma unroll 4
        for (int kk = 0; kk < 16; kk++) {
            const int k = kq * 32 + ((kk + kq * 2) & 15) * 2;   // rotate: no bank clash
            u32 hp = *(const u32*)(ph + k * 2);
            u32 lp = *(const u32*)(pl + k * 2);
            float2 vh = __half22float2(*(__half2*)&hp);
            float2 vl = __half22float2(*(__half2*)&lp);
            float v0 = vh.x + vl.x, v1 = vh.y + vl.y;
            float2 w0 = *(const float2*)(wos + k * 2);
            float2 w1 = *(const float2*)(wos + k * 2 + 2);
            o0 += v0 * w0.x + v1 * w1.x;
            o1 += v0 * w0.y + v1 * w1.y;
        }
        o0 += __shfl_xor_sync(0xffffffffu, o0, 1);
        o0 += __shfl_xor_sync(0xffffffffu, o0, 2);
        o0 += __shfl_xor_sync(0xffffffffu, o0, 4);
        o1 += __shfl_xor_sync(0xffffffffu, o1, 1);
        o1 += __shfl_xor_sync(0xffffffffu, o1, 2);
        o1 += __shfl_xor_sync(0xffffffffu, o1, 4);
        if (kq == 0) {
            if ((m & 7) == 0) { o0 += __ldg(bo); o1 += __ldg(bo + 1); }
            ((float*)(smem + SM_OUT))[m * 2 + 0] = o0;
            ((float*)(smem + SM_OUT))[m * 2 + 1] = o1;
        }
    }
    __syncthreads();

    // ---- per-sample combine + stores
    if (tid < SAMPLES) {
        const float* ob = (const float*)(smem + SM_OUT) + tid * 16;  // [ch][dout]
        float c  = ob[0], Fi = ob[1];
        float cj[4], Fj[4];
#pragma unroll
        for (int i = 0; i < 4; i++) { cj[i] = ob[(1 + i) * 2]; Fj[i] = ob[(1 + i) * 2 + 1]; }
        float trHc = 0.f, FiLap = 0.f;
#pragma unroll
        for (int i = 0; i < 3; i++) { trHc += ob[(5 + i) * 2]; FiLap += ob[(5 + i) * 2 + 1]; }
        float dotg = cj[0] * Fj[0] + cj[1] * Fj[1] + cj[2] * Fj[2];
        float sumg = cj[0] + cj[1] + cj[2];
        float jdiv = -trHc - (dotg + c * FiLap) + 0.1f * sumg;

        const int idx = s0 + tid;
        out[idx]                     = c;
        out[BATCH + idx]             = cj[3];
        out[2 * BATCH + idx * 3 + 0] = cj[0];
        out[2 * BATCH + idx * 3 + 1] = cj[1];
        out[2 * BATCH + idx * 3 + 2] = cj[2];
        out[5 * BATCH + idx]         = Fi;
        out[6 * BATCH + idx * 3 + 0] = Fj[0];
        out[6 * BATCH + idx * 3 + 1] = Fj[1];
        out[6 * BATCH + idx * 3 + 2] = Fj[2];
        out[9 * BATCH + idx]         = FiLap;
        out[10 * BATCH + idx]        = jdiv;
    }
}

extern "C" void kernel_launch(void* const* d_in, const int* in_sizes, int n_in,
                              void* d_out, int out_size) {
    const float* x  = (const float*)d_in[0];
    const float* W0 = (const float*)d_in[1];
    const float* b0 = (const float*)d_in[2];
    const float* W1 = (const float*)d_in[3];
    const float* b1 = (const float*)d_in[4];
    const float* W2 = (const float*)d_in[5];
    const float* b2 = (const float*)d_in[6];
    const float* W3 = (const float*)d_in[7];
    const float* b3 = (const float*)d_in[8];
    const float* Wo = (const float*)d_in[9];
    const float* bo = (const float*)d_in[10];

    prep_split<<<NLAYER * HD, HD>>>(W1, W2, W3);

    cudaFuncSetAttribute(grad_kernel, cudaFuncAttributeMaxDynamicSharedMemorySize, SM_TOT);
    grad_kernel<<<BATCH / SAMPLES, NTHREADS, SM_TOT>>>(x, W0, b0, b1, b2, b3,
                                                       Wo, bo, (float*)d_out);
}